// round 15
// baseline (speedup 1.0000x reference)
#include <cuda_runtime.h>
#include <cuda_fp16.h>
#include <cstdint>
#include <cstddef>

// ---------------- problem constants ----------------
#define DETER   4096
#define STOCH   1024
#define ACT     512
#define HIDDEN  2048
#define CATK    (STOCH + ACT)   // 1536
#define EPS     1e-4f
#define MAXB    16384

// ---------------- scratch (static device globals; allocation-free) ---------
__device__ __align__(256) __half g_cat16[(size_t)MAXB * CATK];     //  48 MB
__device__ __align__(256) float  g_h[(size_t)MAXB * HIDDEN];       // 128 MB
__device__ __align__(256) __half g_h16[(size_t)MAXB * HIDDEN];     //  64 MB
__device__ __align__(256) float  g_x[(size_t)MAXB * DETER];        // 256 MB (x + b2)
__device__ __align__(256) __half g_x16[(size_t)MAXB * DETER];      // 128 MB
__device__ __align__(256) float  g_raw[4][(size_t)MAXB * DETER];   //   1 GB
// fp16 weights: [w1 | w2 | dt | b | c | z]
#define OFF_W1 0
#define OFF_W2 (OFF_W1 + HIDDEN * CATK)
#define OFF_DT (OFF_W2 + DETER * HIDDEN)
#define OFF_B  (OFF_DT + DETER * DETER)
#define OFF_C  (OFF_B  + DETER * DETER)
#define OFF_Z  (OFF_C  + DETER * DETER)
#define W16_TOT (OFF_Z + DETER * DETER)
__device__ __align__(256) __half g_w16[(size_t)W16_TOT];           // 157 MB

#include <mma.h>
using namespace nvcuda;

// ---------------- cp.async helpers ----------------
__device__ __forceinline__ uint32_t smem_u32(const void* p) {
    uint32_t a;
    asm("{ .reg .u64 t; cvta.to.shared.u64 t, %1; cvt.u32.u64 %0, t; }"
        : "=r"(a) : "l"(p));
    return a;
}
#define CP_ASYNC16(dst, src) \
    asm volatile("cp.async.cg.shared.global [%0], [%1], 16;" \
                 :: "r"(dst), "l"(src) : "memory")
#define CP_COMMIT() asm volatile("cp.async.commit_group;" ::: "memory")
#define CP_WAIT(n)  asm volatile("cp.async.wait_group %0;" :: "n"(n) : "memory")

// ================= fp16 WMMA GEMM  C[M,N] = A[M,K] @ W[N,K]^T  =============
// L2-bandwidth fix on the R10 base: block tile 128x256 via 512 threads /
// 16 warps, KEEPING the proven 64x32 warp tile (warp grid 2 x 8).
// L2 bytes/KFLOP drop 32 -> 24 (chunk: 48 KB for 2 MFLOP), bringing chip
// demand under the ~6300 B/cyc LTS cap. Same 16 warps/SM as R10's 2x256.
// Mainloop structure (BK=32, 4 stages, single barrier/chunk) unchanged.
constexpr int BM = 128, BN = 256, BK = 32, STAGES = 4;
constexpr int NTHREADS = 512;
constexpr int LDSH = BK + 8;                        // 40 halves (80 B row)
constexpr int STAGE_HALVES = (BM + BN) * LDSH;      // 15360 halves per stage
constexpr int GEMM_SMEM = STAGES * STAGE_HALVES * 2;  // 122880 bytes

__global__ void __launch_bounds__(NTHREADS, 1)
gemm_h16_kernel(const __half* __restrict__ A,
                const __half* __restrict__ W0, const __half* __restrict__ W1,
                const __half* __restrict__ W2, const __half* __restrict__ W3,
                float* __restrict__ C0, int M, int N, int K)
{
    extern __shared__ __align__(128) __half sm[];

    const __half* W = W0;
    float* C = C0;
    if (gridDim.z > 1) {
        int z = blockIdx.z;
        W = (z == 0) ? W0 : (z == 1) ? W1 : (z == 2) ? W2 : W3;
        C = C0 + (size_t)z * (size_t)M * (size_t)N;
    }

    const int tid = threadIdx.x;
    const int wid = tid >> 5;
    const int wm  = wid & 1;           // 2 warp-rows (64 rows each)
    const int wn  = wid >> 1;          // 8 warp-cols (32 cols each)
    const int m0  = blockIdx.y * BM;
    const int n0  = blockIdx.x * BN;
    const int NC  = K / BK;

    // ---- stage loader: (128+256) rows x 4 chunks of 16B = 1536; 512 thr x 3
    auto load_stage = [&](int st, int kt) {
        uint32_t sb = smem_u32(sm + st * STAGE_HALVES);
        #pragma unroll
        for (int r = 0; r < 3; r++) {
            int i   = tid + r * NTHREADS;     // 0..1535
            int row = i >> 2;                 // 0..383
            int c8  = (i & 3) << 3;           // 0,8,16,24
            const __half* src = (row < BM)
                ? A + (size_t)(m0 + row) * K + kt + c8
                : W + (size_t)(n0 + row - BM) * K + kt + c8;
            CP_ASYNC16(sb + (row * LDSH + c8) * 2, src);
        }
    };

    wmma::fragment<wmma::accumulator, 16, 16, 16, float> acc[4][2];
    #pragma unroll
    for (int i = 0; i < 4; i++)
        #pragma unroll
        for (int j = 0; j < 2; j++)
            wmma::fill_fragment(acc[i][j], 0.0f);

    // ---- prologue: stages 0..STAGES-2 ----
    #pragma unroll
    for (int s = 0; s < STAGES - 1; s++) {
        load_stage(s, s * BK);
        CP_COMMIT();
    }

    // ---- main loop: ONE barrier per chunk (R10 structure) ----
    for (int c = 0; c < NC; c++) {
        CP_WAIT(STAGES - 2);
        __syncthreads();

        int cn = c + STAGES - 1;
        if (cn < NC) load_stage(cn % STAGES, cn * BK);
        CP_COMMIT();

        const __half* as = sm + (c % STAGES) * STAGE_HALVES;
        const __half* ws = as + BM * LDSH;

        #pragma unroll
        for (int kk = 0; kk < BK; kk += 16) {
            wmma::fragment<wmma::matrix_a, 16, 16, 16, __half, wmma::row_major> af[4];
            wmma::fragment<wmma::matrix_b, 16, 16, 16, __half, wmma::col_major> bf[2];
            #pragma unroll
            for (int i = 0; i < 4; i++)
                wmma::load_matrix_sync(af[i], as + (wm * 64 + i * 16) * LDSH + kk, LDSH);
            #pragma unroll
            for (int j = 0; j < 2; j++)
                wmma::load_matrix_sync(bf[j], ws + (wn * 32 + j * 16) * LDSH + kk, LDSH);
            #pragma unroll
            for (int i = 0; i < 4; i++)
                #pragma unroll
                for (int j = 0; j < 2; j++)
                    wmma::mma_sync(acc[i][j], af[i], bf[j], acc[i][j]);
        }
    }

    // ---- store raw fp32 (direct, R10 style; biases folded by consumers) ----
    #pragma unroll
    for (int i = 0; i < 4; i++)
        #pragma unroll
        for (int j = 0; j < 2; j++) {
            size_t off = (size_t)(m0 + wm * 64 + i * 16) * N + (n0 + wn * 32 + j * 16);
            wmma::store_matrix_sync(C + off, acc[i][j], N, wmma::mem_row_major);
        }
}

// ================= elementwise kernels ======================================
__device__ __forceinline__ float block_sum_256(float v)
{
    __shared__ float sh[8];
    __shared__ float total;
    int lane = threadIdx.x & 31, wid = threadIdx.x >> 5;
    #pragma unroll
    for (int o = 16; o; o >>= 1) v += __shfl_xor_sync(0xffffffffu, v, o);
    if (lane == 0) sh[wid] = v;
    __syncthreads();
    if (wid == 0) {
        float t = (lane < 8) ? sh[lane] : 0.0f;
        #pragma unroll
        for (int o = 4; o; o >>= 1) t += __shfl_xor_sync(0xffffffffu, t, o);
        if (lane == 0) total = t;
    }
    __syncthreads();
    return total;
}
__device__ __forceinline__ float softplus_f(float x)
{
    return fmaxf(x, 0.0f) + log1pf(expf(-fabsf(x)));
}

// fp32 -> fp16 bulk convert
__global__ void f2h_kernel(const float* __restrict__ src,
                           __half* __restrict__ dst, int n4)
{
    int i = blockIdx.x * blockDim.x + threadIdx.x;
    if (i >= n4) return;
    float4 v = ((const float4*)src)[i];
    __half2* d = (__half2*)(dst + (size_t)i * 4);
    d[0] = __floats2half2_rn(v.x, v.y);
    d[1] = __floats2half2_rn(v.z, v.w);
}

// cat16 = fp16(concat(stoch, action/max(|action|,1)))
__global__ void concat_h_kernel(const float* __restrict__ st,
                                const float* __restrict__ ac,
                                __half* __restrict__ out, int n4)
{
    int i = blockIdx.x * blockDim.x + threadIdx.x;
    if (i >= n4) return;
    int row = i / (CATK / 4), c = i % (CATK / 4);
    float4 v;
    if (c < STOCH / 4) {
        v = ((const float4*)(st + (size_t)row * STOCH))[c];
    } else {
        v = ((const float4*)(ac + (size_t)row * ACT))[c - STOCH / 4];
        v.x /= fmaxf(fabsf(v.x), 1.0f);
        v.y /= fmaxf(fabsf(v.y), 1.0f);
        v.z /= fmaxf(fabsf(v.z), 1.0f);
        v.w /= fmaxf(fabsf(v.w), 1.0f);
    }
    __half2* d = (__half2*)(out + (size_t)i * 4);
    d[0] = __floats2half2_rn(v.x, v.y);
    d[1] = __floats2half2_rn(v.z, v.w);
}

// h16 = fp16(silu(rmsnorm(h_raw + b1, nw)))   (width 2048)
__global__ void rmsnorm_silu_kernel(const float* __restrict__ h,
                                    __half* __restrict__ h16,
                                    const float* __restrict__ b1,
                                    const float* __restrict__ nw)
{
    const float* p = h + (size_t)blockIdx.x * HIDDEN;
    __half* q = h16 + (size_t)blockIdx.x * HIDDEN;
    float v[8];
    float ss = 0.0f;
    #pragma unroll
    for (int i = 0; i < 8; i++) {
        int c = threadIdx.x + i * 256;
        float t = p[c] + b1[c];
        v[i] = t; ss += t * t;
    }
    ss = block_sum_256(ss);
    float rs = rsqrtf(ss * (1.0f / HIDDEN) + EPS);
    #pragma unroll
    for (int i = 0; i < 8; i++) {
        int c = threadIdx.x + i * 256;
        float u = v[i] * rs * nw[c];
        q[c] = __float2half_rn(u / (1.0f + expf(-u)));
    }
}

// xb = x + b2 (in place, fp32) and x16 = fp16(xb)
__global__ void xbias_kernel(float* __restrict__ x, __half* __restrict__ x16,
                             const float* __restrict__ b2, int n4)
{
    int i = blockIdx.x * blockDim.x + threadIdx.x;
    if (i >= n4) return;
    int c = i & (DETER / 4 - 1);
    float4 v = ((float4*)x)[i];
    float4 b = ((const float4*)b2)[c];
    v.x += b.x; v.y += b.y; v.z += b.z; v.w += b.w;
    ((float4*)x)[i] = v;
    __half2* d = (__half2*)(x16 + (size_t)i * 4);
    d[0] = __floats2half2_rn(v.x, v.y);
    d[1] = __floats2half2_rn(v.z, v.w);
}

// fused SSM update + final rmsnorm -> d_out.  One block per row (width 4096).
__global__ void ssm_norm_kernel(const float* __restrict__ xb,
                                const float* __restrict__ deter,
                                const float* __restrict__ r_dt,
                                const float* __restrict__ r_b,
                                const float* __restrict__ r_c,
                                const float* __restrict__ r_z,
                                const float* __restrict__ dtb,
                                const float* __restrict__ bb,
                                const float* __restrict__ cb,
                                const float* __restrict__ zb,
                                const float* __restrict__ a_base,
                                const float* __restrict__ skip,
                                const float* __restrict__ norm_w,
                                float* __restrict__ out)
{
    const size_t base = (size_t)blockIdx.x * DETER;
    float v[16];
    float ss = 0.0f;
    #pragma unroll
    for (int i = 0; i < 16; i++) {
        int n = threadIdx.x + i * 256;
        size_t g = base + n;

        float xv = xb[g];
        float dt = softplus_f(r_dt[g] + dtb[n]) + 1e-4f;
        float bv = tanhf(r_b[g] + bb[n]);
        float cv = r_c[g] + cb[n];
        float zv = 1.0f / (1.0f + expf(-(r_z[g] + zb[n])));
        float av = -softplus_f(a_base[n]);
        float dv = deter[g];

        float state = expf(av * dt) * dv + dt * bv * xv;
        float y     = cv * state + skip[n] * xv;
        float o     = zv * y + (1.0f - zv) * dv;
        v[i] = o; ss += o * o;
    }
    ss = block_sum_256(ss);
    float rs = rsqrtf(ss * (1.0f / DETER) + EPS);
    #pragma unroll
    for (int i = 0; i < 16; i++) {
        int n = threadIdx.x + i * 256;
        out[base + n] = v[i] * rs * norm_w[n];
    }
}

// ================= host side ================================================
extern "C" void kernel_launch(void* const* d_in, const int* in_sizes, int n_in,
                              void* d_out, int out_size)
{
    const float* stoch  = (const float*)d_in[0];
    const float* deter  = (const float*)d_in[1];
    const float* action = (const float*)d_in[2];
    const float* tok_w1 = (const float*)d_in[3];
    const float* tok_b1 = (const float*)d_in[4];
    const float* tok_nw = (const float*)d_in[5];
    const float* tok_w2 = (const float*)d_in[6];
    const float* tok_b2 = (const float*)d_in[7];
    const float* a_base = (const float*)d_in[8];
    const float* dt_w   = (const float*)d_in[9];
    const float* dt_b   = (const float*)d_in[10];
    const float* b_w    = (const float*)d_in[11];
    const float* b_b    = (const float*)d_in[12];
    const float* c_w    = (const float*)d_in[13];
    const float* c_b    = (const float*)d_in[14];
    const float* z_w    = (const float*)d_in[15];
    const float* z_b    = (const float*)d_in[16];
    const float* skip   = (const float*)d_in[17];
    const float* norm_w = (const float*)d_in[18];
    float* out = (float*)d_out;

    const int B = in_sizes[0] / STOCH;      // 16384

    __half *cat16, *h16, *x16, *w16;
    float *h, *x, *raw;
    cudaGetSymbolAddress((void**)&cat16, g_cat16);
    cudaGetSymbolAddress((void**)&h,     g_h);
    cudaGetSymbolAddress((void**)&h16,   g_h16);
    cudaGetSymbolAddress((void**)&x,     g_x);
    cudaGetSymbolAddress((void**)&x16,   g_x16);
    cudaGetSymbolAddress((void**)&raw,   g_raw);
    cudaGetSymbolAddress((void**)&w16,   g_w16);
    const size_t slab = (size_t)B * DETER;

    cudaFuncSetAttribute(gemm_h16_kernel,
                         cudaFuncAttributeMaxDynamicSharedMemorySize, GEMM_SMEM);

    // ---- convert weights to fp16 ----
    auto conv = [&](const float* src, __half* dst, size_t n) {
        int n4 = (int)(n / 4);
        f2h_kernel<<<(n4 + 255) / 256, 256>>>(src, dst, n4);
    };
    conv(tok_w1, w16 + OFF_W1, (size_t)HIDDEN * CATK);
    conv(tok_w2, w16 + OFF_W2, (size_t)DETER * HIDDEN);
    conv(dt_w,   w16 + OFF_DT, (size_t)DETER * DETER);
    conv(b_w,    w16 + OFF_B,  (size_t)DETER * DETER);
    conv(c_w,    w16 + OFF_C,  (size_t)DETER * DETER);
    conv(z_w,    w16 + OFF_Z,  (size_t)DETER * DETER);

    // ---- cat16 = fp16(concat(stoch, action_norm)) ----
    {
        int n4 = B * (CATK / 4);
        concat_h_kernel<<<(n4 + 255) / 256, 256>>>(stoch, action, cat16, n4);
    }

    // ---- G1: h_raw = cat16 @ w1^T   [B, 2048] ----
    gemm_h16_kernel<<<dim3(HIDDEN / BN, B / BM, 1), NTHREADS, GEMM_SMEM>>>(
        cat16, w16 + OFF_W1, nullptr, nullptr, nullptr, h, B, HIDDEN, CATK);

    // ---- h16 = fp16(silu(rmsnorm(h_raw + b1, nw))) ----
    rmsnorm_silu_kernel<<<B, 256>>>(h, h16, tok_b1, tok_nw);

    // ---- G2: x = h16 @ w2^T   [B, 4096] ----
    gemm_h16_kernel<<<dim3(DETER / BN, B / BM, 1), NTHREADS, GEMM_SMEM>>>(
        h16, w16 + OFF_W2, nullptr, nullptr, nullptr, x, B, DETER, HIDDEN);

    // ---- xb = x + b2 (fp32, in place) ; x16 = fp16(xb) ----
    {
        int n4 = (int)(slab / 4);
        xbias_kernel<<<(n4 + 255) / 256, 256>>>(x, x16, tok_b2, n4);
    }

    // ---- G3..G6: raw[z] = x16 @ {dt,b,c,z}_w^T   4 x [B, 4096] ----
    gemm_h16_kernel<<<dim3(DETER / BN, B / BM, 4), NTHREADS, GEMM_SMEM>>>(
        x16, w16 + OFF_DT, w16 + OFF_B, w16 + OFF_C, w16 + OFF_Z,
        raw, B, DETER, DETER);

    // ---- fused SSM update + final rmsnorm -> d_out ----
    ssm_norm_kernel<<<B, 256>>>(
        x, deter, raw, raw + slab, raw + 2 * slab, raw + 3 * slab,
        dt_b, b_b, c_b, z_b, a_base, skip, norm_w, out);
}

// round 16
// speedup vs baseline: 1.1017x; 1.1017x over previous
#include <cuda_runtime.h>
#include <cuda_fp16.h>
#include <cstdint>
#include <cstddef>

// ---------------- problem constants ----------------
#define DETER   4096
#define STOCH   1024
#define ACT     512
#define HIDDEN  2048
#define CATK    (STOCH + ACT)   // 1536
#define EPS     1e-4f
#define MAXB    16384

// ---------------- scratch (static device globals; allocation-free) ---------
__device__ __align__(256) __half g_cat16[(size_t)MAXB * CATK];     //  48 MB
__device__ __align__(256) float  g_h[(size_t)MAXB * HIDDEN];       // 128 MB
__device__ __align__(256) __half g_h16[(size_t)MAXB * HIDDEN];     //  64 MB
__device__ __align__(256) float  g_x[(size_t)MAXB * DETER];        // 256 MB (raw G2 out)
__device__ __align__(256) __half g_x16[(size_t)MAXB * DETER];      // 128 MB (x + b2, fp16)
__device__ __align__(256) float  g_raw[4][(size_t)MAXB * DETER];   //   1 GB
// fp16 weights: [w1 | w2 | dt | b | c | z]
#define OFF_W1 0
#define OFF_W2 (OFF_W1 + HIDDEN * CATK)
#define OFF_DT (OFF_W2 + DETER * HIDDEN)
#define OFF_B  (OFF_DT + DETER * DETER)
#define OFF_C  (OFF_B  + DETER * DETER)
#define OFF_Z  (OFF_C  + DETER * DETER)
#define W16_TOT (OFF_Z + DETER * DETER)
__device__ __align__(256) __half g_w16[(size_t)W16_TOT];           // 157 MB

#include <mma.h>
using namespace nvcuda;

// ---------------- cp.async helpers ----------------
__device__ __forceinline__ uint32_t smem_u32(const void* p) {
    uint32_t a;
    asm("{ .reg .u64 t; cvta.to.shared.u64 t, %1; cvt.u32.u64 %0, t; }"
        : "=r"(a) : "l"(p));
    return a;
}
#define CP_ASYNC16(dst, src) \
    asm volatile("cp.async.cg.shared.global [%0], [%1], 16;" \
                 :: "r"(dst), "l"(src) : "memory")
#define CP_COMMIT() asm volatile("cp.async.commit_group;" ::: "memory")
#define CP_WAIT(n)  asm volatile("cp.async.wait_group %0;" :: "n"(n) : "memory")

// ================= fp16 WMMA GEMM  C[M,N] = A[M,K] @ W[N,K]^T  =============
// R10 CHAMPION GEMM — unchanged. 128x128 tile, BK=32, 4 stages, 8 warps @
// 64x32, single barrier per chunk, 2 CTAs/SM. Seven perturbations of this
// core regressed; it is frozen.
constexpr int BM = 128, BN = 128, BK = 32, STAGES = 4;
constexpr int LDSH = BK + 8;                        // 40 halves (80 B row)
constexpr int STAGE_HALVES = BM * LDSH;             // per A or W per stage
constexpr int GEMM_SMEM = STAGES * 2 * STAGE_HALVES * 2;  // 81920 bytes

__global__ void __launch_bounds__(256, 2)
gemm_h16_kernel(const __half* __restrict__ A,
                const __half* __restrict__ W0, const __half* __restrict__ W1,
                const __half* __restrict__ W2, const __half* __restrict__ W3,
                float* __restrict__ C0, int M, int N, int K)
{
    extern __shared__ __align__(128) __half sm[];
    __half* As = sm;                                  // [STAGES][BM][LDSH]
    __half* Ws = sm + STAGES * STAGE_HALVES;          // [STAGES][BN][LDSH]

    const __half* W = W0;
    float* C = C0;
    if (gridDim.z > 1) {
        int z = blockIdx.z;
        W = (z == 0) ? W0 : (z == 1) ? W1 : (z == 2) ? W2 : W3;
        C = C0 + (size_t)z * (size_t)M * (size_t)N;
    }

    const int tid = threadIdx.x;
    const int wid = tid >> 5;
    const int wm  = wid & 1;           // 2 warp-rows (64 rows)
    const int wn  = wid >> 1;          // 4 warp-cols (32 cols)
    const int m0  = blockIdx.y * BM;
    const int n0  = blockIdx.x * BN;
    const int NC  = K / BK;

    // ---- stage loader: 512 chunks of 16B per matrix, 256 threads x 2 ----
    auto load_stage = [&](int st, int kt) {
        uint32_t sa = smem_u32(As + st * STAGE_HALVES);
        uint32_t sw = smem_u32(Ws + st * STAGE_HALVES);
        #pragma unroll
        for (int r = 0; r < 2; r++) {
            int i   = tid + r * 256;          // 0..511
            int row = i >> 2;                 // 0..127
            int c8  = (i & 3) << 3;           // 0,8,16,24
            CP_ASYNC16(sa + (row * LDSH + c8) * 2,
                       A + (size_t)(m0 + row) * K + kt + c8);
            CP_ASYNC16(sw + (row * LDSH + c8) * 2,
                       W + (size_t)(n0 + row) * K + kt + c8);
        }
    };

    wmma::fragment<wmma::accumulator, 16, 16, 16, float> acc[4][2];
    #pragma unroll
    for (int i = 0; i < 4; i++)
        #pragma unroll
        for (int j = 0; j < 2; j++)
            wmma::fill_fragment(acc[i][j], 0.0f);

    // ---- prologue: stages 0..STAGES-2 ----
    #pragma unroll
    for (int s = 0; s < STAGES - 1; s++) {
        load_stage(s, s * BK);
        CP_COMMIT();
    }

    // ---- main loop: ONE barrier per chunk ----
    for (int c = 0; c < NC; c++) {
        CP_WAIT(STAGES - 2);
        __syncthreads();

        int cn = c + STAGES - 1;
        if (cn < NC) load_stage(cn % STAGES, cn * BK);
        CP_COMMIT();

        const __half* as = As + (c % STAGES) * STAGE_HALVES;
        const __half* ws = Ws + (c % STAGES) * STAGE_HALVES;

        #pragma unroll
        for (int kk = 0; kk < BK; kk += 16) {
            wmma::fragment<wmma::matrix_a, 16, 16, 16, __half, wmma::row_major> af[4];
            wmma::fragment<wmma::matrix_b, 16, 16, 16, __half, wmma::col_major> bf[2];
            #pragma unroll
            for (int i = 0; i < 4; i++)
                wmma::load_matrix_sync(af[i], as + (wm * 64 + i * 16) * LDSH + kk, LDSH);
            #pragma unroll
            for (int j = 0; j < 2; j++)
                wmma::load_matrix_sync(bf[j], ws + (wn * 32 + j * 16) * LDSH + kk, LDSH);
            #pragma unroll
            for (int i = 0; i < 4; i++)
                #pragma unroll
                for (int j = 0; j < 2; j++)
                    wmma::mma_sync(acc[i][j], af[i], bf[j], acc[i][j]);
        }
    }

    // ---- store raw fp32 (biases folded by consumers) ----
    #pragma unroll
    for (int i = 0; i < 4; i++)
        #pragma unroll
        for (int j = 0; j < 2; j++) {
            size_t off = (size_t)(m0 + wm * 64 + i * 16) * N + (n0 + wn * 32 + j * 16);
            wmma::store_matrix_sync(C + off, acc[i][j], N, wmma::mem_row_major);
        }
}

// ================= elementwise kernels ======================================
__device__ __forceinline__ float block_sum_256(float v)
{
    __shared__ float sh[8];
    __shared__ float total;
    int lane = threadIdx.x & 31, wid = threadIdx.x >> 5;
    #pragma unroll
    for (int o = 16; o; o >>= 1) v += __shfl_xor_sync(0xffffffffu, v, o);
    if (lane == 0) sh[wid] = v;
    __syncthreads();
    if (wid == 0) {
        float t = (lane < 8) ? sh[lane] : 0.0f;
        #pragma unroll
        for (int o = 4; o; o >>= 1) t += __shfl_xor_sync(0xffffffffu, t, o);
        if (lane == 0) total = t;
    }
    __syncthreads();
    return total;
}
__device__ __forceinline__ float softplus_f(float x)
{
    return fmaxf(x, 0.0f) + log1pf(expf(-fabsf(x)));
}

// fp32 -> fp16 bulk convert
__global__ void f2h_kernel(const float* __restrict__ src,
                           __half* __restrict__ dst, int n4)
{
    int i = blockIdx.x * blockDim.x + threadIdx.x;
    if (i >= n4) return;
    float4 v = ((const float4*)src)[i];
    __half2* d = (__half2*)(dst + (size_t)i * 4);
    d[0] = __floats2half2_rn(v.x, v.y);
    d[1] = __floats2half2_rn(v.z, v.w);
}

// cat16 = fp16(concat(stoch, action/max(|action|,1)))
__global__ void concat_h_kernel(const float* __restrict__ st,
                                const float* __restrict__ ac,
                                __half* __restrict__ out, int n4)
{
    int i = blockIdx.x * blockDim.x + threadIdx.x;
    if (i >= n4) return;
    int row = i / (CATK / 4), c = i % (CATK / 4);
    float4 v;
    if (c < STOCH / 4) {
        v = ((const float4*)(st + (size_t)row * STOCH))[c];
    } else {
        v = ((const float4*)(ac + (size_t)row * ACT))[c - STOCH / 4];
        v.x /= fmaxf(fabsf(v.x), 1.0f);
        v.y /= fmaxf(fabsf(v.y), 1.0f);
        v.z /= fmaxf(fabsf(v.z), 1.0f);
        v.w /= fmaxf(fabsf(v.w), 1.0f);
    }
    __half2* d = (__half2*)(out + (size_t)i * 4);
    d[0] = __floats2half2_rn(v.x, v.y);
    d[1] = __floats2half2_rn(v.z, v.w);
}

// h16 = fp16(silu(rmsnorm(h_raw + b1, nw)))   (width 2048)
__global__ void rmsnorm_silu_kernel(const float* __restrict__ h,
                                    __half* __restrict__ h16,
                                    const float* __restrict__ b1,
                                    const float* __restrict__ nw)
{
    const float* p = h + (size_t)blockIdx.x * HIDDEN;
    __half* q = h16 + (size_t)blockIdx.x * HIDDEN;
    float v[8];
    float ss = 0.0f;
    #pragma unroll
    for (int i = 0; i < 8; i++) {
        int c = threadIdx.x + i * 256;
        float t = p[c] + b1[c];
        v[i] = t; ss += t * t;
    }
    ss = block_sum_256(ss);
    float rs = rsqrtf(ss * (1.0f / HIDDEN) + EPS);
    #pragma unroll
    for (int i = 0; i < 8; i++) {
        int c = threadIdx.x + i * 256;
        float u = v[i] * rs * nw[c];
        q[c] = __float2half_rn(u / (1.0f + expf(-u)));
    }
}

// x16 = fp16(x + b2)   (x left untouched; only the fp16 copy is written)
__global__ void xbias_kernel(const float* __restrict__ x,
                             __half* __restrict__ x16,
                             const float* __restrict__ b2, int n4)
{
    int i = blockIdx.x * blockDim.x + threadIdx.x;
    if (i >= n4) return;
    int c = i & (DETER / 4 - 1);
    float4 v = ((const float4*)x)[i];
    float4 b = ((const float4*)b2)[c];
    v.x += b.x; v.y += b.y; v.z += b.z; v.w += b.w;
    __half2* d = (__half2*)(x16 + (size_t)i * 4);
    d[0] = __floats2half2_rn(v.x, v.y);
    d[1] = __floats2half2_rn(v.z, v.w);
}

// fused SSM update + final rmsnorm -> d_out.  One block per row (width 4096).
// xb now read as fp16 (x + b2), halving the x-side read traffic.
__global__ void ssm_norm_kernel(const __half* __restrict__ xb16,
                                const float* __restrict__ deter,
                                const float* __restrict__ r_dt,
                                const float* __restrict__ r_b,
                                const float* __restrict__ r_c,
                                const float* __restrict__ r_z,
                                const float* __restrict__ dtb,
                                const float* __restrict__ bb,
                                const float* __restrict__ cb,
                                const float* __restrict__ zb,
                                const float* __restrict__ a_base,
                                const float* __restrict__ skip,
                                const float* __restrict__ norm_w,
                                float* __restrict__ out)
{
    const size_t base = (size_t)blockIdx.x * DETER;
    float v[16];
    float ss = 0.0f;
    #pragma unroll
    for (int i = 0; i < 16; i++) {
        int n = threadIdx.x + i * 256;
        size_t g = base + n;

        float xv = __half2float(xb16[g]);
        float dt = softplus_f(r_dt[g] + dtb[n]) + 1e-4f;
        float bv = tanhf(r_b[g] + bb[n]);
        float cv = r_c[g] + cb[n];
        float zv = 1.0f / (1.0f + expf(-(r_z[g] + zb[n])));
        float av = -softplus_f(a_base[n]);
        float dv = deter[g];

        float state = expf(av * dt) * dv + dt * bv * xv;
        float y     = cv * state + skip[n] * xv;
        float o     = zv * y + (1.0f - zv) * dv;
        v[i] = o; ss += o * o;
    }
    ss = block_sum_256(ss);
    float rs = rsqrtf(ss * (1.0f / DETER) + EPS);
    #pragma unroll
    for (int i = 0; i < 16; i++) {
        int n = threadIdx.x + i * 256;
        out[base + n] = v[i] * rs * norm_w[n];
    }
}

// ================= host side ================================================
extern "C" void kernel_launch(void* const* d_in, const int* in_sizes, int n_in,
                              void* d_out, int out_size)
{
    const float* stoch  = (const float*)d_in[0];
    const float* deter  = (const float*)d_in[1];
    const float* action = (const float*)d_in[2];
    const float* tok_w1 = (const float*)d_in[3];
    const float* tok_b1 = (const float*)d_in[4];
    const float* tok_nw = (const float*)d_in[5];
    const float* tok_w2 = (const float*)d_in[6];
    const float* tok_b2 = (const float*)d_in[7];
    const float* a_base = (const float*)d_in[8];
    const float* dt_w   = (const float*)d_in[9];
    const float* dt_b   = (const float*)d_in[10];
    const float* b_w    = (const float*)d_in[11];
    const float* b_b    = (const float*)d_in[12];
    const float* c_w    = (const float*)d_in[13];
    const float* c_b    = (const float*)d_in[14];
    const float* z_w    = (const float*)d_in[15];
    const float* z_b    = (const float*)d_in[16];
    const float* skip   = (const float*)d_in[17];
    const float* norm_w = (const float*)d_in[18];
    float* out = (float*)d_out;

    const int B = in_sizes[0] / STOCH;      // 16384

    __half *cat16, *h16, *x16, *w16;
    float *h, *x, *raw;
    cudaGetSymbolAddress((void**)&cat16, g_cat16);
    cudaGetSymbolAddress((void**)&h,     g_h);
    cudaGetSymbolAddress((void**)&h16,   g_h16);
    cudaGetSymbolAddress((void**)&x,     g_x);
    cudaGetSymbolAddress((void**)&x16,   g_x16);
    cudaGetSymbolAddress((void**)&raw,   g_raw);
    cudaGetSymbolAddress((void**)&w16,   g_w16);
    const size_t slab = (size_t)B * DETER;

    cudaFuncSetAttribute(gemm_h16_kernel,
                         cudaFuncAttributeMaxDynamicSharedMemorySize, GEMM_SMEM);

    // ---- convert weights to fp16 ----
    auto conv = [&](const float* src, __half* dst, size_t n) {
        int n4 = (int)(n / 4);
        f2h_kernel<<<(n4 + 255) / 256, 256>>>(src, dst, n4);
    };
    conv(tok_w1, w16 + OFF_W1, (size_t)HIDDEN * CATK);
    conv(tok_w2, w16 + OFF_W2, (size_t)DETER * HIDDEN);
    conv(dt_w,   w16 + OFF_DT, (size_t)DETER * DETER);
    conv(b_w,    w16 + OFF_B,  (size_t)DETER * DETER);
    conv(c_w,    w16 + OFF_C,  (size_t)DETER * DETER);
    conv(z_w,    w16 + OFF_Z,  (size_t)DETER * DETER);

    // ---- cat16 = fp16(concat(stoch, action_norm)) ----
    {
        int n4 = B * (CATK / 4);
        concat_h_kernel<<<(n4 + 255) / 256, 256>>>(stoch, action, cat16, n4);
    }

    // ---- G1: h_raw = cat16 @ w1^T   [B, 2048] ----
    gemm_h16_kernel<<<dim3(HIDDEN / BN, B / BM, 1), 256, GEMM_SMEM>>>(
        cat16, w16 + OFF_W1, nullptr, nullptr, nullptr, h, B, HIDDEN, CATK);

    // ---- h16 = fp16(silu(rmsnorm(h_raw + b1, nw))) ----
    rmsnorm_silu_kernel<<<B, 256>>>(h, h16, tok_b1, tok_nw);

    // ---- G2: x = h16 @ w2^T   [B, 4096] ----
    gemm_h16_kernel<<<dim3(DETER / BN, B / BM, 1), 256, GEMM_SMEM>>>(
        h16, w16 + OFF_W2, nullptr, nullptr, nullptr, x, B, DETER, HIDDEN);

    // ---- x16 = fp16(x + b2)  (single write; x left as-is) ----
    {
        int n4 = (int)(slab / 4);
        xbias_kernel<<<(n4 + 255) / 256, 256>>>(x, x16, tok_b2, n4);
    }

    // ---- G3..G6: raw[z] = x16 @ {dt,b,c,z}_w^T   4 x [B, 4096] ----
    gemm_h16_kernel<<<dim3(DETER / BN, B / BM, 4), 256, GEMM_SMEM>>>(
        x16, w16 + OFF_DT, w16 + OFF_B, w16 + OFF_C, w16 + OFF_Z,
        raw, B, DETER, DETER);

    // ---- fused SSM update + final rmsnorm -> d_out (x read as fp16) ----
    ssm_norm_kernel<<<B, 256>>>(
        x16, deter, raw, raw + slab, raw + 2 * slab, raw + 3 * slab,
        dt_b, b_b, c_b, z_b, a_base, skip, norm_w, out);
}